// round 10
// baseline (speedup 1.0000x reference)
#include <cuda_runtime.h>
#include <math.h>
#include <stdint.h>

// RVQE: 12-qubit real statevector recurrent cell, B=64, T=9 (8 scan steps).
// One CTA per batch element; state = 4096 floats = 128 threads x 16 packed f32x2.
// Global amplitude index g12, g12 = (t << 5) | r (t: 7 bits, r: 5 bits):
//   r bits: bit0=lane11(anc1), bit1=lane10(anc0), bit2=lane9(PACKED),
//           bit3=lane8, bit4=lane7
//   t bits 0..4 (warp lane): lanes 6,5,4,3,2 -> __shfl_xor (mask 1<<(6-lane))
//   t bits 5,6 (warp id):    lanes 1,0      -> smem exchange
// PACKING: P[j], j = b*8 + a*4 + i; i=(anc0<<1)|anc1, a=lane8, b=lane7.
//   P[j].lo = lane9=0, P[j].hi = lane9=1. All rotations packed f32x2 FMA.
//
// Fused neuron algebra (validated rounds 3/5/8): per stage
//   chain = E(a_0) C_0 G_0 T'(D1) C_1 G_1 ... T'(D9) C_9 G_9 F(a_9)
// Sync scheme: 3 smem exchanges/stage (ry4, ciy lane0, ciy lane1), ping-pong
// buffers A/B, ONE __syncthreads per exchange (reuse-at-distance-2 ordered by
// the intermediate exchange's sync). 7 syncs/step total, 4-warp CTA.

namespace {

typedef unsigned long long u64;

constexpr int NTH   = 128;
constexpr int TT    = 9;
constexpr int NSTEP = 8;
constexpr int NIDX  = 22;   // 18 deltas + 2 entries + 2 trailings
constexpr int ST    = 17;   // exch stride in u64 (16+1; odd -> conflict-free 64b)
constexpr u64 SGN2  = 0x8000000080000000ULL;

__device__ __forceinline__ u64 pk(float lo, float hi) {
    u64 r; asm("mov.b64 %0,{%1,%2};" : "=l"(r) : "f"(lo), "f"(hi)); return r;
}
__device__ __forceinline__ void upk(u64 u, float& lo, float& hi) {
    asm("mov.b64 {%0,%1},%2;" : "=f"(lo), "=f"(hi) : "l"(u));
}
__device__ __forceinline__ u64 bc(float x) { return pk(x, x); }
__device__ __forceinline__ u64 f2mul(u64 a, u64 b) {
    u64 d; asm("mul.rn.f32x2 %0,%1,%2;" : "=l"(d) : "l"(a), "l"(b)); return d;
}
__device__ __forceinline__ u64 f2fma(u64 a, u64 b, u64 c) {
    u64 d; asm("fma.rn.f32x2 %0,%1,%2,%3;" : "=l"(d) : "l"(a), "l"(b), "l"(c)); return d;
}
__device__ __forceinline__ u64 f2neg(u64 a) { return a ^ SGN2; }
__device__ __forceinline__ u64 f2swap(u64 a) { float lo, hi; upk(a, lo, hi); return pk(hi, lo); }

// ---- stage RY pieces ----

// RY on lane9 (packed dim): u' = C*u + (-s,+s)*swap(u)
__device__ __forceinline__ void ry_lane9(u64* P, u64 C, u64 SW) {
#pragma unroll
    for (int j = 0; j < 16; j++)
        P[j] = f2fma(SW, f2swap(P[j]), f2mul(C, P[j]));
}

// RY on lane8 (a bit): pairs (j, j|4) within each b group
__device__ __forceinline__ void ry_lane8(u64* P, float c, float s) {
    u64 C = bc(c), S = bc(s), NS = bc(-s);
#pragma unroll
    for (int b2 = 0; b2 < 2; b2++)
#pragma unroll
        for (int i = 0; i < 4; i++) {
            int j = b2 * 8 + i;
            u64 u = P[j], w = P[j + 4];
            P[j]     = f2fma(NS, w, f2mul(C, u));
            P[j + 4] = f2fma(S,  u, f2mul(C, w));
        }
}

// RY on lane7 (b bit): pairs (j, j|8)
__device__ __forceinline__ void ry_lane7(u64* P, float c, float s) {
    u64 C = bc(c), S = bc(s), NS = bc(-s);
#pragma unroll
    for (int j = 0; j < 8; j++) {
        u64 u = P[j], w = P[j + 8];
        P[j]     = f2fma(NS, w, f2mul(C, u));
        P[j + 8] = f2fma(S,  u, f2mul(C, w));
    }
}

__device__ __forceinline__ void ry_shfl(u64* P, int t, int m, float c, float s) {
    u64 C = bc(c), SE = bc((t & m) ? s : -s);
#pragma unroll
    for (int j = 0; j < 16; j++) {
        u64 w = __shfl_xor_sync(0xffffffffu, P[j], m);
        P[j] = f2fma(SE, w, f2mul(C, P[j]));
    }
}

// Combined RY(lane0)*RY(lane1) on t bits 6,5: one sync, 4-way gather.
__device__ __forceinline__ void ry_smem4(u64* P, int t,
                                         float c0, float s0, float c1, float s1,
                                         u64* X) {
#pragma unroll
    for (int j = 0; j < 16; j++) X[t * ST + j] = P[j];
    __syncthreads();
    int a  = (t >> 6) & 1;   // lane0 bit
    int bb = (t >> 5) & 1;   // lane1 bit
    float r0a0 = a  ? s0 : c0;
    float r0a1 = a  ? c0 : -s0;
    float r1b0 = bb ? s1 : c1;
    float r1b1 = bb ? c1 : -s1;
    u64 k00 = bc(r0a0 * r1b0), k01 = bc(r0a0 * r1b1);
    u64 k10 = bc(r0a1 * r1b0), k11 = bc(r0a1 * r1b1);
    int base = t & 31;
    const u64* x00 = X + base * ST;
    const u64* x01 = X + (base | 32) * ST;
    const u64* x10 = X + (base | 64) * ST;
    const u64* x11 = X + (base | 96) * ST;
#pragma unroll
    for (int j = 0; j < 16; j++)
        P[j] = f2fma(k00, x00[j],
               f2fma(k01, x01[j],
               f2fma(k10, x10[j], f2mul(k11, x11[j]))));
    // no trailing sync: next exchange (other buffer) provides ordering
}

// ---- CiY pieces (ctrl anc1: odd i -> odd j) ----

__device__ __forceinline__ void ciy_lane9(u64* P) {
#pragma unroll
    for (int j = 1; j < 16; j += 2) {
        float lo, hi; upk(P[j], lo, hi);
        P[j] = pk(hi, -lo);
    }
}

// target lane8 (a bit)
__device__ __forceinline__ void ciy_lane8(u64* P) {
#pragma unroll
    for (int b2 = 0; b2 < 2; b2++)
#pragma unroll
        for (int i = 1; i < 4; i += 2) {
            int j = b2 * 8 + i;
            u64 p0 = P[j];
            P[j] = P[j + 4];
            P[j + 4] = f2neg(p0);
        }
}

// target lane7 (b bit)
__device__ __forceinline__ void ciy_lane7(u64* P) {
#pragma unroll
    for (int j = 1; j < 8; j += 2) {
        u64 p0 = P[j];
        P[j] = P[j + 8];
        P[j + 8] = f2neg(p0);
    }
}

__device__ __forceinline__ void ciy_shfl(u64* P, int t, int m) {
    u64 sgn = (t & m) ? SGN2 : 0ULL;
#pragma unroll
    for (int j = 1; j < 16; j += 2) {
        u64 w = __shfl_xor_sync(0xffffffffu, P[j], m);
        P[j] = w ^ sgn;
    }
}

// Cross-warp CiY: one sync, ping-pong buffer.
__device__ __forceinline__ void ciy_smem(u64* P, int t, int m, u64* X) {
#pragma unroll
    for (int j = 1; j < 16; j += 2) X[t * ST + (j >> 1)] = P[j];
    __syncthreads();
    const u64* p = X + (t ^ m) * ST;
    u64 sgn = (t & m) ? SGN2 : 0ULL;
#pragma unroll
    for (int j = 1; j < 16; j += 2) P[j] = p[j >> 1] ^ sgn;
}

// ---- fused neuron ops (packed over lane9; loop over k = b*2+a) ----
// x_i = P[4k+i]: x0=(0,0) x1=(0,1) x2=(1,0) x3=(1,1) of (anc0,anc1)

__device__ __forceinline__ void applyT(u64* P, float cb, float sb,
                                       const u64* DC, const u64* DS) {
    u64 CB = bc(cb), SB = bc(sb), NSB = bc(-sb);
#pragma unroll
    for (int k = 0; k < 4; k++) {
        u64 C  = f2fma(NSB, DS[k], f2mul(CB, DC[k]));
        u64 S  = f2fma(SB,  DC[k], f2mul(CB, DS[k]));
        u64 NS = f2neg(S);
        u64 x0 = P[4*k+0], x1 = P[4*k+1], x2 = P[4*k+2], x3 = P[4*k+3];
        P[4*k+0] = f2fma(S,  x3, f2mul(C, x0));
        P[4*k+1] = f2fma(NS, x2, f2mul(C, x1));
        P[4*k+2] = f2fma(S,  x1, f2mul(C, x2));
        P[4*k+3] = f2fma(NS, x0, f2mul(C, x3));
    }
}

__device__ __forceinline__ void applyE(u64* P, float cb, float sb,
                                       const u64* DC, const u64* DS) {
    u64 CB = bc(cb), SB = bc(sb), NSB = bc(-sb);
#pragma unroll
    for (int k = 0; k < 4; k++) {
        u64 C  = f2fma(NSB, DS[k], f2mul(CB, DC[k]));
        u64 S  = f2fma(SB,  DC[k], f2mul(CB, DS[k]));
        u64 NS = f2neg(S);
        u64 x0 = P[4*k+0], x1 = P[4*k+1], x2 = P[4*k+2], x3 = P[4*k+3];
        P[4*k+0] = f2fma(NS, x2, f2mul(C, x0));
        P[4*k+1] = f2fma(NS, x3, f2mul(C, x1));
        P[4*k+2] = f2fma(S,  x1, f2mul(C, x3));
        P[4*k+3] = f2neg(f2fma(S, x0, f2mul(C, x2)));
    }
}

__device__ __forceinline__ void applyF(u64* P, float cb, float sb,
                                       const u64* DC, const u64* DS) {
    u64 CB = bc(cb), SB = bc(sb), NSB = bc(-sb);
#pragma unroll
    for (int k = 0; k < 4; k++) {
        u64 C  = f2fma(NSB, DS[k], f2mul(CB, DC[k]));
        u64 S  = f2fma(SB,  DC[k], f2mul(CB, DS[k]));
        u64 NS = f2neg(S);
        u64 x0 = P[4*k+0], x1 = P[4*k+1], x2 = P[4*k+2], x3 = P[4*k+3];
        P[4*k+0] = f2fma(NS, x3, f2mul(C, x0));
        P[4*k+1] = f2fma(S,  x2, f2mul(C, x1));
        P[4*k+2] = f2neg(f2fma(S, x0, f2mul(C, x3)));
        P[4*k+3] = f2fma(NS, x1, f2mul(C, x2));
    }
}

// G: rotate (x1,x3) in each group k by signed angle SE[k].
__device__ __forceinline__ void applyG4(u64* P, u64 C, const u64* SE) {
#pragma unroll
    for (int k = 0; k < 4; k++) {
        u64 x1 = P[4*k+1], x3 = P[4*k+3];
        P[4*k+1] = f2fma(f2neg(SE[k]), x3, f2mul(C, x1));
        P[4*k+3] = f2fma(SE[k],        x1, f2mul(C, x3));
    }
}

// angle-vector spec tables
__device__ constexpr int aIdx[NIDX] = {1,2,3,4,5,6,7,8,9, 11,12,13,14,15,16,17,18,19, 0, 10, 9, 19};
__device__ constexpr int bIdx[NIDX] = {0,1,2,3,4,5,6,7,8, 10,11,12,13,14,15,16,17,18, -1,-1,-1,-1};

__global__ void __launch_bounds__(NTH, 1) rvqe_kernel(
    const int*   __restrict__ inputs,   // (64, 9, 6) int32
    const float* __restrict__ ua,       // (2, 10)
    const float* __restrict__ nth,      // (2, 10, 11)
    float*       __restrict__ out,
    int out_size)
{
    __shared__ u64   bufA[NTH * ST];    // 17408 B
    __shared__ u64   bufB[NTH * ST];    // 17408 B
    __shared__ float uc[20], us[20];
    __shared__ u64   DC2[NIDX][4], DS2[NIDX][4];  // delta trig per (b,a), packed lane9
    __shared__ float gc_sm[20], gs_sm[20];
    __shared__ u64   se9p[2];
    __shared__ float probs_sm[64];
    __shared__ int   tIdx[TT];

    const int t = threadIdx.x;
    const int b = blockIdx.x;
    const int* inb = inputs + b * TT * 6;

    // ---- precompute ----
    if (t < 20) {
        float c, s; sincosf(0.5f * ua[t], &s, &c);
        uc[t] = c; us[t] = s;
        float cg, sg; sincosf(0.5f * nth[t * 11 + (t % 10)], &sg, &cg);
        gc_sm[t] = cg; gs_sm[t] = sg;
        if ((t % 10) == 9) se9p[t / 10] = pk(-sg, sg);
    }
    // delta trig: k = b*2 + a over lanes 7,8; packed halves over lane9
    if (t < NIDX * 4) {
        int idx = t >> 2, k = t & 3, b2 = k >> 1, a = k & 1;
        const float* A = nth + aIdx[idx] * 11;
        const float* Bp = (bIdx[idx] >= 0) ? (nth + bIdx[idx] * 11) : nullptr;
        float d7 = A[7] - (Bp ? Bp[7] : 0.f);
        float d8 = A[8] - (Bp ? Bp[8] : 0.f);
        float d9 = A[9] - (Bp ? Bp[9] : 0.f);
        float dlo = b2 * d7 + a * d8;
        float dhi = dlo + d9;
        float cl, sl, ch, sh;
        sincosf(0.5f * dlo, &sl, &cl);
        sincosf(0.5f * dhi, &sh, &ch);
        DC2[idx][k] = pk(cl, ch);
        DS2[idx][k] = pk(sl, sh);
    }
    if (t < TT) {
        int idx = 0;
#pragma unroll
        for (int i = 0; i < 6; i++) idx |= (inb[t * 6 + i] & 1) << (5 - i);
        tIdx[t] = idx;
    }

    // per-thread base trig in REGISTERS (lane i -> t bit (6-i), i=0..6)
    float cbs[NIDX], sbs[NIDX];
#pragma unroll
    for (int idx = 0; idx < NIDX; idx++) {
        const float* A = nth + aIdx[idx] * 11;
        const float* Bp = (bIdx[idx] >= 0) ? (nth + bIdx[idx] * 11) : nullptr;
        float base = A[10] - (Bp ? Bp[10] : 0.f);
#pragma unroll
        for (int i = 0; i < 7; i++)
            if ((t >> (6 - i)) & 1) base += A[i] - (Bp ? Bp[i] : 0.f);
        float c, s; sincosf(0.5f * base, &s, &c);
        cbs[idx] = c; sbs[idx] = s;
    }
    __syncthreads();

    // ---- init state: g12 = tIdx[0]<<6 -> thread tIdx[0]<<1, r=0 (lo of P[0]) ----
    u64 P[16];
#pragma unroll
    for (int j = 0; j < 16; j++) P[j] = 0ULL;
    if (t == (tIdx[0] << 1)) P[0] = pk(1.f, 0.f);

    for (int step = 0; step < NSTEP; step++) {
#pragma unroll
        for (int s = 0; s < 2; s++) {
            const float* ucc = uc + s * 10;
            const float* uss = us + s * 10;
            u64* bR  = (s == 0) ? bufA : bufB;   // ry4
            u64* bC0 = (s == 0) ? bufB : bufA;   // ciy lane0
            u64* bC1 = (s == 0) ? bufA : bufB;   // ciy lane1

            // stage RYs: lanes 7,8 cross-reg; lane9 packed; lanes 2..6 shfl; 0,1 smem
            ry_lane7(P, ucc[7], uss[7]);
            ry_lane8(P, ucc[8], uss[8]);
            {
                u64 C9 = bc(ucc[9]);
                u64 SW = pk(-uss[9], uss[9]);
                ry_lane9(P, C9, SW);
            }
#pragma unroll
            for (int l = 2; l <= 6; l++)
                ry_shfl(P, t, 1 << (6 - l), ucc[l], uss[l]);
            ry_smem4(P, t, ucc[0], uss[0], ucc[1], uss[1], bR);

            // neuron chain: E C0 G0 T' C1 G1 ... T' C9 G9 F
            applyE(P, cbs[18 + s], sbs[18 + s], DC2[18 + s], DS2[18 + s]);
            ciy_smem(P, t, 64, bC0);                 // C0 (lane0 = t bit6)
            {
                u64 SEu = bc(((t >> 6) & 1) ? gs_sm[s * 10] : -gs_sm[s * 10]);
                u64 SE[4] = {SEu, SEu, SEu, SEu};
                applyG4(P, bc(gc_sm[s * 10]), SE);
            }
#pragma unroll
            for (int n = 1; n < 10; n++) {
                int di = s * 9 + n - 1;
                applyT(P, cbs[di], sbs[di], DC2[di], DS2[di]);
                if (n == 9)      ciy_lane9(P);
                else if (n == 8) ciy_lane8(P);
                else if (n == 7) ciy_lane7(P);
                else if (n >= 2) ciy_shfl(P, t, 1 << (6 - n));
                else             ciy_smem(P, t, 32, bC1);   // C1 (lane1 = t bit5)

                int gi = s * 10 + n;
                u64 C = bc(gc_sm[gi]);
                if (n <= 6) {
                    u64 SEu = bc(((t >> (6 - n)) & 1) ? gs_sm[gi] : -gs_sm[gi]);
                    u64 SE[4] = {SEu, SEu, SEu, SEu};
                    applyG4(P, C, SE);
                } else if (n == 7) {          // sign from b bit (k>=2)
                    u64 Sp = bc(gs_sm[gi]), Sn = f2neg(Sp);
                    u64 SE[4] = {Sn, Sn, Sp, Sp};
                    applyG4(P, C, SE);
                } else if (n == 8) {          // sign from a bit (k odd)
                    u64 Sp = bc(gs_sm[gi]), Sn = f2neg(Sp);
                    u64 SE[4] = {Sn, Sp, Sn, Sp};
                    applyG4(P, C, SE);
                } else {                      // n == 9: packed sign
                    u64 SEu = se9p[s];
                    u64 SE[4] = {SEu, SEu, SEu, SEu};
                    applyG4(P, C, SE);
                }
            }
            applyF(P, cbs[20 + s], sbs[20 + s], DC2[20 + s], DS2[20 + s]);
        }

        // ---- probs: out j = t >> 1 (lanes 0..5 = t bits 6..1); reduce bit0+local ----
        u64 acc = 0ULL;
#pragma unroll
        for (int j = 0; j < 16; j++) acc = f2fma(P[j], P[j], acc);
        float alo, ahi; upk(acc, alo, ahi);
        float ssq = alo + ahi;
        ssq += __shfl_xor_sync(0xffffffffu, ssq, 1);
        if (!(t & 1)) {
            probs_sm[t >> 1] = ssq;
            out[(b * NSTEP + step) * 64 + (t >> 1)] = ssq;
        }
        __syncthreads();

        // ---- project + normalize; cond_flips cancel across steps ----
        int tj = tIdx[step + 1];
        float invn = 1.0f / sqrtf(probs_sm[tj]);
        if ((t >> 1) == tj) {
            u64 INV = bc(invn);
#pragma unroll
            for (int j = 0; j < 16; j++) P[j] = f2mul(INV, P[j]);
        } else {
#pragma unroll
            for (int j = 0; j < 16; j++) P[j] = 0ULL;
        }
    }

    // ---- second tuple output: measured = inputs[:,1:] as float ----
    if (out_size > 32768 && t < 48) {
        out[32768 + b * 48 + t] = (float)inb[6 + t];
    }
}

} // namespace

extern "C" void kernel_launch(void* const* d_in, const int* in_sizes, int n_in,
                              void* d_out, int out_size) {
    const int*   inputs = nullptr;
    const float* ua     = nullptr;
    const float* nth    = nullptr;
    for (int i = 0; i < n_in; i++) {
        if (in_sizes[i] == 3456)      inputs = (const int*)d_in[i];
        else if (in_sizes[i] == 20)   ua     = (const float*)d_in[i];
        else if (in_sizes[i] == 220)  nth    = (const float*)d_in[i];
    }
    rvqe_kernel<<<64, NTH>>>(inputs, ua, nth, (float*)d_out, out_size);
}

// round 11
// speedup vs baseline: 1.1958x; 1.1958x over previous
#include <cuda_runtime.h>
#include <math.h>
#include <stdint.h>

// RVQE: 12-qubit real statevector recurrent cell, B=64, T=9 (8 scan steps).
// One CTA per batch element; state = 4096 floats = 256 threads x 8 packed f32x2.
// Global amplitude index g12 (12 bits), g12 = (t << 4) | r:
//   r bits: bit0=lane11(anc1), bit1=lane10(anc0), bit2=lane9(PACKED), bit3=lane8
//   t bits 0..4 (warp lane): lanes 7,6,5,4,3  -> __shfl_xor (mask 1<<(7-lane))
//   t bits 5,6,7: lanes 2,1,0 -> smem exchange
// PACKING: P[j], j = a*4 + i, i = (anc0<<1)|anc1, a = lane8 bit.
//   P[j].lo = lane9=0, P[j].hi = lane9=1. All rotations are packed f32x2 FMA.
//
// Fused neuron algebra (validated rounds 3/5/8): per stage
//   chain = E(a_0) C_0 G_0 T'(D1) C_1 G_1 ... T'(D9) C_9 G_9 F(a_9)
//
// Sync scheme (this round): each smem exchange = write, ONE __syncthreads,
// read — no trailing sync. Ping-pong buffers A/B alternate across the 5
// exchanges per stage (A,B,A,B,A / B,A,B,A,B), so any reuse of a buffer is
// separated by the other buffer's sync (partner's read of A precedes its
// write of B precedes B's sync precedes the next write of A).
// 5 syncs/stage vs 10 in round 8.

namespace {

typedef unsigned long long u64;

constexpr int NTH   = 256;
constexpr int TT    = 9;
constexpr int NSTEP = 8;
constexpr int NIDX  = 22;   // 18 deltas + 2 entries + 2 trailings
constexpr int STq   = 9;    // exch stride in u64 (8 + 1 pad; odd -> conflict-free)
constexpr u64 SGN2  = 0x8000000080000000ULL;

__device__ __forceinline__ u64 pk(float lo, float hi) {
    u64 r; asm("mov.b64 %0,{%1,%2};" : "=l"(r) : "f"(lo), "f"(hi)); return r;
}
__device__ __forceinline__ void upk(u64 u, float& lo, float& hi) {
    asm("mov.b64 {%0,%1},%2;" : "=f"(lo), "=f"(hi) : "l"(u));
}
__device__ __forceinline__ u64 bc(float x) { return pk(x, x); }
__device__ __forceinline__ u64 f2mul(u64 a, u64 b) {
    u64 d; asm("mul.rn.f32x2 %0,%1,%2;" : "=l"(d) : "l"(a), "l"(b)); return d;
}
__device__ __forceinline__ u64 f2fma(u64 a, u64 b, u64 c) {
    u64 d; asm("fma.rn.f32x2 %0,%1,%2,%3;" : "=l"(d) : "l"(a), "l"(b), "l"(c)); return d;
}
__device__ __forceinline__ u64 f2neg(u64 a) { return a ^ SGN2; }
__device__ __forceinline__ u64 f2swap(u64 a) { float lo, hi; upk(a, lo, hi); return pk(hi, lo); }

// ---- stage RY pieces ----

// RY on lane9 (the packed dim): u' = C*u + (-s,+s)*swap(u)
__device__ __forceinline__ void ry_lane9(u64* P, u64 C, u64 SW) {
#pragma unroll
    for (int j = 0; j < 8; j++)
        P[j] = f2fma(SW, f2swap(P[j]), f2mul(C, P[j]));
}

// RY on lane8 (a bit): cross-reg, element-wise packed
__device__ __forceinline__ void ry_lane8(u64* P, float c, float s) {
    u64 C = bc(c), S = bc(s), NS = bc(-s);
#pragma unroll
    for (int i = 0; i < 4; i++) {
        u64 u = P[i], w = P[4 + i];
        P[i]     = f2fma(NS, w, f2mul(C, u));
        P[4 + i] = f2fma(S,  u, f2mul(C, w));
    }
}

__device__ __forceinline__ void ry_shfl(u64* P, int t, int m, float c, float s) {
    u64 C = bc(c), SE = bc((t & m) ? s : -s);
#pragma unroll
    for (int j = 0; j < 8; j++) {
        u64 w = __shfl_xor_sync(0xffffffffu, P[j], m);
        P[j] = f2fma(SE, w, f2mul(C, P[j]));
    }
}

// Combined RY(lane0)*RY(lane1) (t bits 7,6): one sync, 4-way gather.
__device__ __forceinline__ void ry_smem4(u64* P, int t,
                                         float c0, float s0, float c1, float s1,
                                         u64* X) {
#pragma unroll
    for (int j = 0; j < 8; j++) X[t * STq + j] = P[j];
    __syncthreads();
    int a  = (t >> 7) & 1;
    int bb = (t >> 6) & 1;
    float r0a0 = a  ? s0 : c0;
    float r0a1 = a  ? c0 : -s0;
    float r1b0 = bb ? s1 : c1;
    float r1b1 = bb ? c1 : -s1;
    u64 k00 = bc(r0a0 * r1b0), k01 = bc(r0a0 * r1b1);
    u64 k10 = bc(r0a1 * r1b0), k11 = bc(r0a1 * r1b1);
    int base = t & 63;
    const u64* x00 = X + base * STq;
    const u64* x01 = X + (base | 64)  * STq;
    const u64* x10 = X + (base | 128) * STq;
    const u64* x11 = X + (base | 192) * STq;
#pragma unroll
    for (int j = 0; j < 8; j++)
        P[j] = f2fma(k00, x00[j],
               f2fma(k01, x01[j],
               f2fma(k10, x10[j], f2mul(k11, x11[j]))));
    // no trailing sync: ping-pong ordering
}

// RY on lane2 (t bit5): 2-way exchange, one sync.
__device__ __forceinline__ void ry_smem1(u64* P, int t, float c, float s, u64* X) {
#pragma unroll
    for (int j = 0; j < 8; j++) X[t * STq + j] = P[j];
    __syncthreads();
    const u64* xp = X + (t ^ 32) * STq;
    u64 C = bc(c), SE = bc((t & 32) ? s : -s);
#pragma unroll
    for (int j = 0; j < 8; j++) P[j] = f2fma(SE, xp[j], f2mul(C, P[j]));
    // no trailing sync: ping-pong ordering
}

// ---- CiY pieces (ctrl anc1: odd j) ----

__device__ __forceinline__ void ciy_lane9(u64* P) {
#pragma unroll
    for (int j = 1; j < 8; j += 2) {
        float lo, hi; upk(P[j], lo, hi);
        P[j] = pk(hi, -lo);
    }
}

__device__ __forceinline__ void ciy_lane8(u64* P) {
#pragma unroll
    for (int i = 1; i < 4; i += 2) {
        u64 p0 = P[i];
        P[i] = P[4 + i];
        P[4 + i] = f2neg(p0);
    }
}

__device__ __forceinline__ void ciy_shfl(u64* P, int t, int m) {
    u64 sgn = (t & m) ? SGN2 : 0ULL;
#pragma unroll
    for (int j = 1; j < 8; j += 2) {
        u64 w = __shfl_xor_sync(0xffffffffu, P[j], m);
        P[j] = w ^ sgn;
    }
}

// Cross-warp CiY: one sync, ping-pong buffer.
__device__ __forceinline__ void ciy_smem(u64* P, int t, int m, u64* X) {
#pragma unroll
    for (int j = 1; j < 8; j += 2) X[t * STq + (j >> 1)] = P[j];
    __syncthreads();
    const u64* p = X + (t ^ m) * STq;
    u64 sgn = (t & m) ? SGN2 : 0ULL;
#pragma unroll
    for (int j = 1; j < 8; j += 2) P[j] = p[j >> 1] ^ sgn;
    // no trailing sync: ping-pong ordering
}

// ---- fused neuron ops (packed over lane9; loop over a = lane8 bit) ----
// x_i = P[a*4+i]: x0=(0,0) x1=(0,1) x2=(1,0) x3=(1,1) of (anc0,anc1)

__device__ __forceinline__ void applyT(u64* P, float cb, float sb,
                                       const u64* DC, const u64* DS) {
    u64 CB = bc(cb), SB = bc(sb), NSB = bc(-sb);
#pragma unroll
    for (int a = 0; a < 2; a++) {
        u64 C  = f2fma(NSB, DS[a], f2mul(CB, DC[a]));
        u64 S  = f2fma(SB,  DC[a], f2mul(CB, DS[a]));
        u64 NS = f2neg(S);
        u64 x0 = P[4*a+0], x1 = P[4*a+1], x2 = P[4*a+2], x3 = P[4*a+3];
        P[4*a+0] = f2fma(S,  x3, f2mul(C, x0));
        P[4*a+1] = f2fma(NS, x2, f2mul(C, x1));
        P[4*a+2] = f2fma(S,  x1, f2mul(C, x2));
        P[4*a+3] = f2fma(NS, x0, f2mul(C, x3));
    }
}

__device__ __forceinline__ void applyE(u64* P, float cb, float sb,
                                       const u64* DC, const u64* DS) {
    u64 CB = bc(cb), SB = bc(sb), NSB = bc(-sb);
#pragma unroll
    for (int a = 0; a < 2; a++) {
        u64 C  = f2fma(NSB, DS[a], f2mul(CB, DC[a]));
        u64 S  = f2fma(SB,  DC[a], f2mul(CB, DS[a]));
        u64 NS = f2neg(S);
        u64 x0 = P[4*a+0], x1 = P[4*a+1], x2 = P[4*a+2], x3 = P[4*a+3];
        P[4*a+0] = f2fma(NS, x2, f2mul(C, x0));
        P[4*a+1] = f2fma(NS, x3, f2mul(C, x1));
        P[4*a+2] = f2fma(S,  x1, f2mul(C, x3));
        P[4*a+3] = f2neg(f2fma(S, x0, f2mul(C, x2)));
    }
}

__device__ __forceinline__ void applyF(u64* P, float cb, float sb,
                                       const u64* DC, const u64* DS) {
    u64 CB = bc(cb), SB = bc(sb), NSB = bc(-sb);
#pragma unroll
    for (int a = 0; a < 2; a++) {
        u64 C  = f2fma(NSB, DS[a], f2mul(CB, DC[a]));
        u64 S  = f2fma(SB,  DC[a], f2mul(CB, DS[a]));
        u64 NS = f2neg(S);
        u64 x0 = P[4*a+0], x1 = P[4*a+1], x2 = P[4*a+2], x3 = P[4*a+3];
        P[4*a+0] = f2fma(NS, x3, f2mul(C, x0));
        P[4*a+1] = f2fma(S,  x2, f2mul(C, x1));
        P[4*a+2] = f2neg(f2fma(S, x0, f2mul(C, x3)));
        P[4*a+3] = f2fma(NS, x1, f2mul(C, x2));
    }
}

__device__ __forceinline__ void applyG_se(u64* P, u64 C, u64 SE0, u64 SE1) {
    u64 NSE0 = f2neg(SE0), NSE1 = f2neg(SE1);
    {
        u64 x1 = P[1], x3 = P[3];
        P[1] = f2fma(NSE0, x3, f2mul(C, x1));
        P[3] = f2fma(SE0,  x1, f2mul(C, x3));
    }
    {
        u64 x1 = P[5], x3 = P[7];
        P[5] = f2fma(NSE1, x3, f2mul(C, x1));
        P[7] = f2fma(SE1,  x1, f2mul(C, x3));
    }
}

// angle-vector spec tables
__device__ constexpr int aIdx[NIDX] = {1,2,3,4,5,6,7,8,9, 11,12,13,14,15,16,17,18,19, 0, 10, 9, 19};
__device__ constexpr int bIdx[NIDX] = {0,1,2,3,4,5,6,7,8, 10,11,12,13,14,15,16,17,18, -1,-1,-1,-1};

__global__ void __launch_bounds__(NTH, 1) rvqe_kernel(
    const int*   __restrict__ inputs,   // (64, 9, 6) int32
    const float* __restrict__ ua,       // (2, 10)
    const float* __restrict__ nth,      // (2, 10, 11)
    float*       __restrict__ out,
    int out_size)
{
    __shared__ u64   bufA[NTH * STq];   // 18432 B
    __shared__ u64   bufB[NTH * STq];   // 18432 B
    __shared__ float uc[20], us[20];
    __shared__ u64   DC2[NIDX][2], DS2[NIDX][2];
    __shared__ float gc_sm[20], gs_sm[20];
    __shared__ u64   se9p[2];
    __shared__ float probs_sm[64];
    __shared__ int   tIdx[TT];

    const int t = threadIdx.x;
    const int b = blockIdx.x;
    const int* inb = inputs + b * TT * 6;

    // ---- precompute ----
    if (t < 20) {
        float c, s; sincosf(0.5f * ua[t], &s, &c);
        uc[t] = c; us[t] = s;
        float cg, sg; sincosf(0.5f * nth[t * 11 + (t % 10)], &sg, &cg);
        gc_sm[t] = cg; gs_sm[t] = sg;
        if ((t % 10) == 9) se9p[t / 10] = pk(-sg, sg);
    }
    if (t < NIDX * 2) {
        int idx = t >> 1, a = t & 1;
        const float* A = nth + aIdx[idx] * 11;
        const float* Bp = (bIdx[idx] >= 0) ? (nth + bIdx[idx] * 11) : nullptr;
        float d8 = A[8] - (Bp ? Bp[8] : 0.f);
        float d9 = A[9] - (Bp ? Bp[9] : 0.f);
        float dlo = a ? d8 : 0.f;
        float dhi = dlo + d9;
        float cl, sl, ch, sh;
        sincosf(0.5f * dlo, &sl, &cl);
        sincosf(0.5f * dhi, &sh, &ch);
        DC2[idx][a] = pk(cl, ch);
        DS2[idx][a] = pk(sl, sh);
    }
    if (t < TT) {
        int idx = 0;
#pragma unroll
        for (int i = 0; i < 6; i++) idx |= (inb[t * 6 + i] & 1) << (5 - i);
        tIdx[t] = idx;
    }

    // per-thread base trig in REGISTERS (lane i -> t bit (7-i), i=0..7)
    float cbs[NIDX], sbs[NIDX];
#pragma unroll
    for (int idx = 0; idx < NIDX; idx++) {
        const float* A = nth + aIdx[idx] * 11;
        const float* Bp = (bIdx[idx] >= 0) ? (nth + bIdx[idx] * 11) : nullptr;
        float base = A[10] - (Bp ? Bp[10] : 0.f);
#pragma unroll
        for (int i = 0; i < 8; i++)
            if ((t >> (7 - i)) & 1) base += A[i] - (Bp ? Bp[i] : 0.f);
        float c, s; sincosf(0.5f * base, &s, &c);
        cbs[idx] = c; sbs[idx] = s;
    }
    __syncthreads();

    // ---- init state ----
    u64 P[8];
#pragma unroll
    for (int j = 0; j < 8; j++) P[j] = 0ULL;
    if (t == (tIdx[0] << 2)) P[0] = pk(1.f, 0.f);

    for (int step = 0; step < NSTEP; step++) {
#pragma unroll
        for (int s = 0; s < 2; s++) {
            const float* ucc = uc + s * 10;
            const float* uss = us + s * 10;
            // ping-pong buffer assignment: exchanges alternate A,B,A,B,A per
            // stage; stage parity flips (5 exchanges per stage).
            u64* e1 = (s == 0) ? bufA : bufB;   // ry_smem4
            u64* e2 = (s == 0) ? bufB : bufA;   // ry_smem1
            u64* e3 = (s == 0) ? bufA : bufB;   // ciy n=0
            u64* e4 = (s == 0) ? bufB : bufA;   // ciy n=1
            u64* e5 = (s == 0) ? bufA : bufB;   // ciy n=2

            // stage RYs: lane8 cross-reg, lane9 packed; lanes 3..7 shfl; 0,1,2 smem
            ry_lane8(P, ucc[8], uss[8]);
            {
                u64 C9 = bc(ucc[9]);
                u64 SW = pk(-uss[9], uss[9]);
                ry_lane9(P, C9, SW);
            }
#pragma unroll
            for (int l = 3; l <= 7; l++)
                ry_shfl(P, t, 1 << (7 - l), ucc[l], uss[l]);
            ry_smem4(P, t, ucc[0], uss[0], ucc[1], uss[1], e1);
            ry_smem1(P, t, ucc[2], uss[2], e2);

            // neuron chain: E C0 G0 T' C1 G1 ... T' C9 G9 F
            applyE(P, cbs[18 + s], sbs[18 + s], DC2[18 + s], DS2[18 + s]);
            ciy_smem(P, t, 128, e3);                   // C0 (lane0 = t bit7)
            {
                float sg = ((t >> 7) & 1) ? gs_sm[s * 10] : -gs_sm[s * 10];
                u64 SE = bc(sg);
                applyG_se(P, bc(gc_sm[s * 10]), SE, SE);
            }
#pragma unroll
            for (int n = 1; n < 10; n++) {
                int di = s * 9 + n - 1;
                applyT(P, cbs[di], sbs[di], DC2[di], DS2[di]);
                if (n == 9) {
                    ciy_lane9(P);
                } else if (n == 8) {
                    ciy_lane8(P);
                } else if (n >= 3) {
                    ciy_shfl(P, t, 1 << (7 - n));
                } else if (n == 1) {
                    ciy_smem(P, t, 64, e4);            // lane1 = t bit6
                } else {
                    ciy_smem(P, t, 32, e5);            // lane2 = t bit5
                }
                int gi = s * 10 + n;
                u64 C = bc(gc_sm[gi]);
                if (n <= 7) {
                    float sg = ((t >> (7 - n)) & 1) ? gs_sm[gi] : -gs_sm[gi];
                    u64 SE = bc(sg);
                    applyG_se(P, C, SE, SE);
                } else if (n == 8) {
                    u64 SE1 = bc(gs_sm[gi]);
                    applyG_se(P, C, f2neg(SE1), SE1);
                } else {
                    u64 SE = se9p[s];
                    applyG_se(P, C, SE, SE);
                }
            }
            applyF(P, cbs[20 + s], sbs[20 + s], DC2[20 + s], DS2[20 + s]);
        }

        // ---- probs: out index j = t >> 2; reduce over t bits 0,1 + packed halves ----
        u64 acc = 0ULL;
#pragma unroll
        for (int j = 0; j < 8; j++) acc = f2fma(P[j], P[j], acc);
        float alo, ahi; upk(acc, alo, ahi);
        float ssq = alo + ahi;
        ssq += __shfl_xor_sync(0xffffffffu, ssq, 1);
        ssq += __shfl_xor_sync(0xffffffffu, ssq, 2);
        if (!(t & 3)) {
            probs_sm[t >> 2] = ssq;
            out[(b * NSTEP + step) * 64 + (t >> 2)] = ssq;
        }
        __syncthreads();

        // ---- project + normalize; cond_flips cancel across steps ----
        int tj = tIdx[step + 1];
        float invn = 1.0f / sqrtf(probs_sm[tj]);
        if ((t >> 2) == tj) {
            u64 INV = bc(invn);
#pragma unroll
            for (int j = 0; j < 8; j++) P[j] = f2mul(INV, P[j]);
        } else {
#pragma unroll
            for (int j = 0; j < 8; j++) P[j] = 0ULL;
        }
    }

    // ---- second tuple output: measured = inputs[:,1:] as float ----
    if (out_size > 32768 && t < 48) {
        out[32768 + b * 48 + t] = (float)inb[6 + t];
    }
}

} // namespace

extern "C" void kernel_launch(void* const* d_in, const int* in_sizes, int n_in,
                              void* d_out, int out_size) {
    const int*   inputs = nullptr;
    const float* ua     = nullptr;
    const float* nth    = nullptr;
    for (int i = 0; i < n_in; i++) {
        if (in_sizes[i] == 3456)      inputs = (const int*)d_in[i];
        else if (in_sizes[i] == 20)   ua     = (const float*)d_in[i];
        else if (in_sizes[i] == 220)  nth    = (const float*)d_in[i];
    }
    rvqe_kernel<<<64, NTH>>>(inputs, ua, nth, (float*)d_out, out_size);
}